// round 11
// baseline (speedup 1.0000x reference)
#include <cuda_runtime.h>
#include <cuda_fp16.h>
#include <math.h>
#include <stdint.h>

#define BATCH 4
#define SEQ   4096
#define EMB   512
#define HD    64
#define BS    (BATCH*SEQ)
#define MT    128
#define NMT   (SEQ/MT)            // 32
#define KT    128
#define TPB   8                   // max key tiles per block
#define BLKS_PER_B 80             // sum_m ceil((m+1)/8)
#define MAXSPLIT 4
#define SCALE_LOG2E 0.06375872036f   // log2(e)/sqrt(512)
#define ONE2 0x3C003C00u             // fp16x2 (1.0, 1.0)

// ---------------- device scratch ----------------
__device__ unsigned g_Qh[BS*32];                    // packed fp16 pairs, [row][32 words]
__device__ unsigned g_Kh[BS*32];
__device__ unsigned g_Vth[BATCH*64*2048];           // V^T packed key-pairs, [b*64+d][2048]
__device__ unsigned g_Wth[192*256];                 // W^T packed: [n(Q64|K64|V64)][256 kw]
__device__ unsigned g_OpartH[(size_t)BATCH*NMT*MAXSPLIT*MT*32];   // fp16x2 partials
__device__ float    g_Lpart[BATCH*NMT*MAXSPLIT*MT];

static __device__ __forceinline__ unsigned packhf(float o, float e) {
    unsigned r;
    asm("cvt.rn.f16x2.f32 %0, %1, %2;" : "=r"(r) : "f"(o), "f"(e));
    return r;
}
static __device__ __forceinline__ float ex2(float x) {
    float r;
    asm("ex2.approx.ftz.f32 %0, %1;" : "=f"(r) : "f"(x));
    return r;
}
static __device__ __forceinline__ uint32_t smem_u32(const void* p) {
    uint32_t a;
    asm("{ .reg .u64 t; cvta.to.shared.u64 t, %1; cvt.u32.u64 %0, t; }" : "=r"(a) : "l"(p));
    return a;
}
static __device__ __forceinline__ void cpa16(uint32_t s, const void* g) {
    asm volatile("cp.async.cg.shared.global [%0], [%1], 16;" :: "r"(s), "l"(g));
}
#define CPA_COMMIT() asm volatile("cp.async.commit_group;" ::: "memory")
#define CPA_WAIT0()  asm volatile("cp.async.wait_group 0;" ::: "memory")
#define CPA_WAIT1()  asm volatile("cp.async.wait_group 1;" ::: "memory")

static __device__ __forceinline__ void ldsm4(unsigned &r0, unsigned &r1,
                                             unsigned &r2, unsigned &r3, uint32_t a) {
    asm volatile("ldmatrix.sync.aligned.m8n8.x4.shared.b16 {%0,%1,%2,%3}, [%4];"
                 : "=r"(r0), "=r"(r1), "=r"(r2), "=r"(r3) : "r"(a));
}

#define MMAH(C, A, b0v, b1v)                                                     \
    asm volatile("mma.sync.aligned.m16n8k16.row.col.f32.f16.f16.f32 "            \
        "{%0,%1,%2,%3}, {%4,%5,%6,%7}, {%8,%9}, {%0,%1,%2,%3};"                  \
        : "+f"((C)[0]), "+f"((C)[1]), "+f"((C)[2]), "+f"((C)[3])                 \
        : "r"((A)[0]), "r"((A)[1]), "r"((A)[2]), "r"((A)[3]), "r"(b0v), "r"(b1v))

// ---------------- W^T prep: [n=192][k=512] -> packed fp16 [n][256 words] --------
__global__ void wprep_kernel(const float* __restrict__ WQ,
                             const float* __restrict__ WK,
                             const float* __restrict__ WV) {
    int n  = blockIdx.x;                 // 0..191
    int kp = threadIdx.x;                // 0..255
    const float* W = (n < 64) ? WQ : (n < 128 ? WK : WV);
    int nc = n & 63;
    float v0 = W[(2*kp)     * 64 + nc];
    float v1 = W[(2*kp + 1) * 64 + nc];
    g_Wth[n*256 + kp] = packhf(v1, v0);
}

// ---------------- QKV projection via fp16 HMMA, double-buffered, ldmatrix --------
#define QX0 0
#define QX1 4608
#define QW0 9216
#define QW1 16128
#define QSMEM_BYTES (23040*4)

__global__ __launch_bounds__(256, 1) void qkv_mma(const float* __restrict__ x) {
    extern __shared__ unsigned qs[];
    const uint32_t sbase = smem_u32(qs);

    const int tid  = threadIdx.x;
    const int w    = tid >> 5;
    const int lane = tid & 31;
    const int g    = lane >> 2;
    const int t4   = lane & 3;
    const long r0  = (long)blockIdx.x * 128;

    const int Lr = lane & 7, Lm = lane >> 3;
    const uint32_t aoff  = (uint32_t)(((w*16 + (Lm&1)*8 + Lr)*36 + (Lm>>1)*4) * 4);
    const uint32_t woffb = (uint32_t)((((Lm>>1)*8 + Lr)*36 + (Lm&1)*4) * 4);

    const int xr = tid >> 1, xhf = tid & 1;
    const int xo = xr*36 + xhf*16;

    float C[24][4];
    #pragma unroll
    for (int j = 0; j < 24; j++)
        #pragma unroll
        for (int i = 0; i < 4; i++) C[j][i] = 0.f;

    // ---- prologue: x(0) regs + W(0) cp.async + STS x(0) ----
    float4 xv[8];
    {
        const float4* xp = (const float4*)&x[(r0 + xr) * EMB + 0 + xhf*32];
        #pragma unroll
        for (int i = 0; i < 8; i++) xv[i] = xp[i];
    }
    {
        uint32_t wb = sbase + QW0*4;
        #pragma unroll
        for (int i = 0; i < 6; i++) {
            int idx = tid + i*256;
            int n = idx >> 3, c4 = idx & 7;
            cpa16(wb + (n*36 + c4*4)*4, g_Wth + n*256 + 0 + c4*4);
        }
    }
    CPA_COMMIT();
    #pragma unroll
    for (int j = 0; j < 4; j++) {
        uint4 pk;
        pk.x = packhf(xv[2*j].y,   xv[2*j].x);
        pk.y = packhf(xv[2*j].w,   xv[2*j].z);
        pk.z = packhf(xv[2*j+1].y, xv[2*j+1].x);
        pk.w = packhf(xv[2*j+1].w, xv[2*j+1].z);
        *(uint4*)&qs[QX0 + xo + j*4] = pk;
    }

    for (int it = 0; it < 8; it++) {
        const int cur = it & 1;
        const int xcur = cur ? QX1 : QX0;
        const int xnxt = cur ? QX0 : QX1;
        const int wcur = cur ? QW1 : QW0;
        const int wnxt = cur ? QW0 : QW1;

        if (it < 7) {
            const float4* xp = (const float4*)&x[(r0 + xr) * EMB + (it+1)*64 + xhf*32];
            #pragma unroll
            for (int i = 0; i < 8; i++) xv[i] = xp[i];
            uint32_t wb = sbase + wnxt*4;
            int kw0 = ((it+1)*64) >> 1;
            #pragma unroll
            for (int i = 0; i < 6; i++) {
                int idx = tid + i*256;
                int n = idx >> 3, c4 = idx & 7;
                cpa16(wb + (n*36 + c4*4)*4, g_Wth + n*256 + kw0 + c4*4);
            }
            CPA_COMMIT();
            CPA_WAIT1();
        } else {
            CPA_WAIT0();
        }
        __syncthreads();

        const uint32_t xb = sbase + xcur*4 + aoff;
        const uint32_t wb2 = sbase + wcur*4 + woffb;
        #pragma unroll
        for (int kk = 0; kk < 4; kk++) {
            unsigned ah[4];
            ldsm4(ah[0], ah[1], ah[2], ah[3], xb + kk*32);
            #pragma unroll
            for (int j2 = 0; j2 < 12; j2++) {
                unsigned b0, b1, b2, b3;
                ldsm4(b0, b1, b2, b3, wb2 + (uint32_t)((j2*2*288 + kk*8) * 4));
                MMAH(C[2*j2],   ah, b0, b1);
                MMAH(C[2*j2+1], ah, b2, b3);
            }
        }

        if (it < 7) {
            #pragma unroll
            for (int j = 0; j < 4; j++) {
                uint4 pk;
                pk.x = packhf(xv[2*j].y,   xv[2*j].x);
                pk.y = packhf(xv[2*j].w,   xv[2*j].z);
                pk.z = packhf(xv[2*j+1].y, xv[2*j+1].x);
                pk.w = packhf(xv[2*j+1].w, xv[2*j+1].z);
                *(uint4*)&qs[xnxt + xo + j*4] = pk;
            }
        }
    }
    __syncthreads();

    // ---- epilogue: Q (j 0..7), K (j 8..15) -> packed fp16 global ----
    const long rowg = r0 + w*16 + g;
    #pragma unroll
    for (int j = 0; j < 16; j++) {
        unsigned* oh = (j < 8) ? g_Qh : g_Kh;
        int wi = (j & 7)*4 + t4;
        oh[rowg*32 + wi]     = packhf(C[j][1], C[j][0]);
        oh[(rowg+8)*32 + wi] = packhf(C[j][3], C[j][2]);
    }

    // ---- V (j 16..23): stage fp32 in smem, transpose+pack to g_Vth ----
    float* vs = (float*)qs;   // [128][66] floats = 8448 w
    #pragma unroll
    for (int j = 16; j < 24; j++) {
        int col = (j - 16)*8 + 2*t4;
        *(float2*)&vs[(w*16 + g)*66 + col]     = make_float2(C[j][0], C[j][1]);
        *(float2*)&vs[(w*16 + g + 8)*66 + col] = make_float2(C[j][2], C[j][3]);
    }
    __syncthreads();

    {
        int b   = (int)(r0 >> 12);
        int kpb = (int)(r0 & 4095) >> 1;
        int kp  = tid & 63;
        int d0  = (tid >> 6) * 16;
        #pragma unroll
        for (int i = 0; i < 16; i++) {
            int d = d0 + i;
            float v0 = vs[(2*kp)*66 + d];
            float v1 = vs[(2*kp + 1)*66 + d];
            g_Vth[((size_t)(b*64 + d)) * 2048 + kpb + kp] = packhf(v1, v0);
        }
    }
}

// ---------------- fp16 HMMA flash attention ----------------
#define BUF_W   8960
#define BK_OFF  0
#define BV_OFF  4608
#define SMEM_BYTES (17920*4)

static __device__ __forceinline__ void attn_issue(uint32_t sbase, int bufw,
                                                  int tid, int b, long brow, int kt) {
    const uint4* KH = (const uint4*)g_Kh + (brow + (long)kt * KT) * 8;
    uint32_t kb = sbase + (bufw + BK_OFF) * 4;
    #pragma unroll
    for (int i = 0; i < 4; i++) {
        int idx = tid + i * 256;
        int r = idx >> 3, c4 = idx & 7;
        cpa16(kb + (r*36 + c4*4)*4, &KH[r*8 + c4]);
    }
    uint32_t vb = sbase + (bufw + BV_OFF) * 4;
    #pragma unroll
    for (int i = 0; i < 4; i++) {
        int idx = tid + i * 256;
        int d = idx >> 4, c4 = idx & 15;
        cpa16(vb + (d*68 + c4*4)*4,
              (const uint4*)g_Vth + ((size_t)(b*64 + d)) * 512 + (size_t)kt * 16 + c4);
    }
}

__global__ __launch_bounds__(256, 2) void attn_mma() {
    extern __shared__ unsigned smw[];
    const uint32_t sbase = smem_u32(smw);

    const int tid  = threadIdx.x;
    const int w    = tid >> 5;
    const int lane = tid & 31;
    const int g    = lane >> 2;
    const int t4   = lane & 3;

    const int Lr = lane & 7, Lm = lane >> 3;
    const uint32_t koff = (uint32_t)((((Lm>>1)*8 + Lr)*36 + (Lm&1)*4) * 4);
    const uint32_t voff = (uint32_t)((((Lm>>1)*8 + Lr)*68 + (Lm&1)*4) * 4);

    // decode (m, split); longest CTAs first
    int rid = (BLKS_PER_B - 1) - (int)blockIdx.x, m = 0, split = 0;
    #pragma unroll 1
    for (int mm = 0; mm < NMT; mm++) {
        int c = (mm + TPB) >> 3;
        if (rid < c) { m = mm; split = rid; break; }
        rid -= c;
    }
    const int b   = blockIdx.y;
    const int kt0 = split * TPB;
    const int kt1 = (kt0 + TPB < m + 1) ? (kt0 + TPB) : (m + 1);
    const long brow = (long)b * SEQ;
    const int rg = m * MT + w * 16 + g;

    // Q fragments (persist across tiles)
    unsigned qh[4][4];
    {
        long base0 = (brow + rg) * 32;
        long base8 = base0 + 8 * 32;
        #pragma unroll
        for (int kk = 0; kk < 4; kk++) {
            int wlo = 8*kk + t4, whi = wlo + 4;
            qh[kk][0] = g_Qh[base0 + wlo]; qh[kk][1] = g_Qh[base8 + wlo];
            qh[kk][2] = g_Qh[base0 + whi]; qh[kk][3] = g_Qh[base8 + whi];
        }
    }

    float O[8][4];
    #pragma unroll
    for (int i = 0; i < 8; i++)
        #pragma unroll
        for (int j = 0; j < 4; j++) O[i][j] = 0.f;
    float lC[4];
    #pragma unroll
    for (int i = 0; i < 4; i++) lC[i] = 0.f;

    attn_issue(sbase, 0, tid, b, brow, kt0);
    CPA_COMMIT();
    int cur = 0;

    for (int kt = kt0; kt < kt1; kt++) {
        CPA_WAIT0();
        __syncthreads();
        if (kt + 1 < kt1) {
            attn_issue(sbase, (cur ^ 1) * BUF_W, tid, b, brow, kt + 1);
            CPA_COMMIT();
        }
        const uint32_t kbb = sbase + (cur * BUF_W + BK_OFF) * 4 + koff;
        const uint32_t vbb = sbase + (cur * BUF_W + BV_OFF) * 4 + voff;

        const int diag = (kt == m);
        const int kbase = kt * KT;

        #pragma unroll
        for (int h = 0; h < 2; h++) {
            if (diag && h*64 > w*16 + 15) continue;   // half fully above diagonal

            float S[8][4];
            #pragma unroll
            for (int j = 0; j < 8; j++)
                #pragma unroll
                for (int r = 0; r < 4; r++) S[j][r] = 0.f;

            #pragma unroll
            for (int kk = 0; kk < 4; kk++) {
                #pragma unroll
                for (int j2 = 0; j2 < 4; j2++) {
                    unsigned b0, b1, b2, b3;
                    ldsm4(b0, b1, b2, b3,
                          kbb + (uint32_t)(((h*8 + j2*2)*288 + kk*8) * 4));
                    MMAH(S[2*j2],   qh[kk], b0, b1);
                    MMAH(S[2*j2+1], qh[kk], b2, b3);
                }
            }

            unsigned ph[4][4];
            #pragma unroll
            for (int j = 0; j < 8; j++) {
                float p0 = ex2(S[j][0] * SCALE_LOG2E);
                float p1 = ex2(S[j][1] * SCALE_LOG2E);
                float p2 = ex2(S[j][2] * SCALE_LOG2E);
                float p3 = ex2(S[j][3] * SCALE_LOG2E);
                if (diag) {
                    int col = kbase + (h*8 + j)*8 + 2*t4;
                    if (col     > rg)     p0 = 0.f;
                    if (col + 1 > rg)     p1 = 0.f;
                    if (col     > rg + 8) p2 = 0.f;
                    if (col + 1 > rg + 8) p3 = 0.f;
                }
                int kk2 = j >> 1, hf = (j & 1) * 2;
                ph[kk2][hf]     = packhf(p1, p0);
                ph[kk2][hf + 1] = packhf(p3, p2);
            }

            #pragma unroll
            for (int kk2 = 0; kk2 < 4; kk2++) {
                #pragma unroll
                for (int n2p = 0; n2p < 4; n2p++) {
                    unsigned b0, b1, b2, b3;
                    ldsm4(b0, b1, b2, b3,
                          vbb + (uint32_t)((n2p*2*544 + (h*4 + kk2)*8) * 4));
                    MMAH(O[2*n2p],   ph[kk2], b0, b1);
                    MMAH(O[2*n2p+1], ph[kk2], b2, b3);
                }
                MMAH(lC, ph[kk2], ONE2, ONE2);   // l row-sum via ones column
            }
        }
        cur ^= 1;
    }

    // ---- write partials (fp16 O, fp32 l from ones-MMA col 0) ----
    const int pidx = (b * NMT + m) * MAXSPLIT + split;
    if (t4 == 0) {
        g_Lpart[pidx*128 + w*16 + g]     = lC[0];
        g_Lpart[pidx*128 + w*16 + g + 8] = lC[2];
    }
    unsigned* op0 = g_OpartH + ((size_t)pidx*128 + w*16 + g) * 32;
    unsigned* op8 = op0 + 8*32;
    #pragma unroll
    for (int n2 = 0; n2 < 8; n2++) {
        op0[n2*4 + t4] = packhf(O[n2][1], O[n2][0]);
        op8[n2*4 + t4] = packhf(O[n2][3], O[n2][2]);
    }
}

// ---------------- combine split partials (fp16 in, 8 floats/thread) ----------------
__global__ void combine_kernel(float* __restrict__ out) {
    int idx8 = blockIdx.x * blockDim.x + threadIdx.x;
    if (idx8 >= BS * 8) return;
    int row = idx8 >> 3, d8 = idx8 & 7;
    int b = row >> 12;
    int s_in_b = row & 4095;
    int m = s_in_b >> 7, r = s_in_b & 127;
    int nsp = (m + TPB) >> 3;
    int p0 = (b * NMT + m) * MAXSPLIT;

    uint4 v[4];
    float l[4];
    #pragma unroll
    for (int s = 0; s < 4; s++) {
        v[s] = make_uint4(0u, 0u, 0u, 0u);
        l[s] = 0.f;
        if (s < nsp) {
            int p = p0 + s;
            v[s] = *(const uint4*)&g_OpartH[((size_t)p * 128 + r) * 32 + d8*4];
            l[s] = g_Lpart[p * 128 + r];
        }
    }
    float acc[8];
    #pragma unroll
    for (int i = 0; i < 8; i++) acc[i] = 0.f;
    #pragma unroll
    for (int s = 0; s < 4; s++) {
        unsigned wd[4] = { v[s].x, v[s].y, v[s].z, v[s].w };
        #pragma unroll
        for (int i = 0; i < 4; i++) {
            float2 f = __half22float2(*(__half2*)&wd[i]);
            acc[2*i]   += f.x;
            acc[2*i+1] += f.y;
        }
    }
    float inv = 1.f / (l[0] + l[1] + l[2] + l[3]);
    float* o = out + (size_t)row * 64 + d8*8;
    *(float4*)o       = make_float4(acc[0]*inv, acc[1]*inv, acc[2]*inv, acc[3]*inv);
    *(float4*)(o + 4) = make_float4(acc[4]*inv, acc[5]*inv, acc[6]*inv, acc[7]*inv);
}

extern "C" void kernel_launch(void* const* d_in, const int* in_sizes, int n_in,
                              void* d_out, int out_size) {
    const float* x  = (const float*)d_in[0];
    const float* WQ = (const float*)d_in[1];
    const float* WK = (const float*)d_in[2];
    const float* WV = (const float*)d_in[3];
    float* out = (float*)d_out;

    cudaFuncSetAttribute(qkv_mma,  cudaFuncAttributeMaxDynamicSharedMemorySize, QSMEM_BYTES);
    cudaFuncSetAttribute(attn_mma, cudaFuncAttributeMaxDynamicSharedMemorySize, SMEM_BYTES);

    wprep_kernel<<<192, 256>>>(WQ, WK, WV);
    qkv_mma<<<BS / 128, 256, QSMEM_BYTES>>>(x);
    attn_mma<<<dim3(BLKS_PER_B, BATCH), 256, SMEM_BYTES>>>();
    combine_kernel<<<(BS * 8 + 255) / 256, 256>>>(out);
}

// round 12
// speedup vs baseline: 1.5159x; 1.5159x over previous
#include <cuda_runtime.h>
#include <cuda_fp16.h>
#include <math.h>
#include <stdint.h>

#define BATCH 4
#define SEQ   4096
#define EMB   512
#define HD    64
#define BS    (BATCH*SEQ)
#define MT    128
#define NMT   (SEQ/MT)            // 32
#define KT    128
#define TPB   8                   // max key tiles per block
#define BLKS_PER_B 80             // sum_m ceil((m+1)/8)
#define MAXSPLIT 4
#define SCALE_LOG2E 0.06375872036f   // log2(e)/sqrt(512)

// ---------------- device scratch ----------------
__device__ unsigned g_Qh[BS*32];                    // packed fp16 pairs, [row][32 words]
__device__ unsigned g_Kh[BS*32];
__device__ unsigned g_Vth[BATCH*64*2048];           // V^T packed key-pairs, [b*64+d][2048]
__device__ unsigned g_Wth[192*256];                 // W^T packed: [n(Q64|K64|V64)][256 kw]
__device__ unsigned g_OpartH[(size_t)BATCH*NMT*MAXSPLIT*MT*32];   // fp16x2 partials
__device__ float    g_Lpart[BATCH*NMT*MAXSPLIT*MT];

static __device__ __forceinline__ unsigned packhf(float o, float e) {
    unsigned r;
    asm("cvt.rn.f16x2.f32 %0, %1, %2;" : "=r"(r) : "f"(o), "f"(e));
    return r;
}
static __device__ __forceinline__ float ex2(float x) {
    float r;
    asm("ex2.approx.ftz.f32 %0, %1;" : "=f"(r) : "f"(x));
    return r;
}
static __device__ __forceinline__ uint32_t smem_u32(const void* p) {
    uint32_t a;
    asm("{ .reg .u64 t; cvta.to.shared.u64 t, %1; cvt.u32.u64 %0, t; }" : "=r"(a) : "l"(p));
    return a;
}
static __device__ __forceinline__ void cpa16(uint32_t s, const void* g) {
    asm volatile("cp.async.cg.shared.global [%0], [%1], 16;" :: "r"(s), "l"(g));
}
#define CPA_COMMIT() asm volatile("cp.async.commit_group;" ::: "memory")
#define CPA_WAIT0()  asm volatile("cp.async.wait_group 0;" ::: "memory")
#define CPA_WAIT1()  asm volatile("cp.async.wait_group 1;" ::: "memory")

static __device__ __forceinline__ void ldsm4(unsigned &r0, unsigned &r1,
                                             unsigned &r2, unsigned &r3, uint32_t a) {
    asm volatile("ldmatrix.sync.aligned.m8n8.x4.shared.b16 {%0,%1,%2,%3}, [%4];"
                 : "=r"(r0), "=r"(r1), "=r"(r2), "=r"(r3) : "r"(a));
}

#define MMAH(C, A, b0v, b1v)                                                     \
    asm volatile("mma.sync.aligned.m16n8k16.row.col.f32.f16.f16.f32 "            \
        "{%0,%1,%2,%3}, {%4,%5,%6,%7}, {%8,%9}, {%0,%1,%2,%3};"                  \
        : "+f"((C)[0]), "+f"((C)[1]), "+f"((C)[2]), "+f"((C)[3])                 \
        : "r"((A)[0]), "r"((A)[1]), "r"((A)[2]), "r"((A)[3]), "r"(b0v), "r"(b1v))

// ---------------- W^T prep: [n=192][k=512] -> packed fp16 [n][256 words] --------
__global__ void wprep_kernel(const float* __restrict__ WQ,
                             const float* __restrict__ WK,
                             const float* __restrict__ WV) {
    int n  = blockIdx.x;                 // 0..191
    int kp = threadIdx.x;                // 0..255
    const float* W = (n < 64) ? WQ : (n < 128 ? WK : WV);
    int nc = n & 63;
    float v0 = W[(2*kp)     * 64 + nc];
    float v1 = W[(2*kp + 1) * 64 + nc];
    g_Wth[n*256 + kp] = packhf(v1, v0);
}

// ---------------- QKV projection via fp16 HMMA, double-buffered, ldmatrix --------
#define QX0 0
#define QX1 4608
#define QW0 9216
#define QW1 16128
#define QSMEM_BYTES (23040*4)

__global__ __launch_bounds__(256, 1) void qkv_mma(const float* __restrict__ x) {
    extern __shared__ unsigned qs[];
    const uint32_t sbase = smem_u32(qs);

    const int tid  = threadIdx.x;
    const int w    = tid >> 5;
    const int lane = tid & 31;
    const int g    = lane >> 2;
    const int t4   = lane & 3;
    const long r0  = (long)blockIdx.x * 128;

    const int Lr = lane & 7, Lm = lane >> 3;
    const uint32_t aoff  = (uint32_t)(((w*16 + (Lm&1)*8 + Lr)*36 + (Lm>>1)*4) * 4);
    const uint32_t woffb = (uint32_t)((((Lm>>1)*8 + Lr)*36 + (Lm&1)*4) * 4);

    const int xr = tid >> 1, xhf = tid & 1;
    const int xo = xr*36 + xhf*16;

    float C[24][4];
    #pragma unroll
    for (int j = 0; j < 24; j++)
        #pragma unroll
        for (int i = 0; i < 4; i++) C[j][i] = 0.f;

    // ---- prologue: x(0) regs + W(0) cp.async + STS x(0) ----
    float4 xv[8];
    {
        const float4* xp = (const float4*)&x[(r0 + xr) * EMB + 0 + xhf*32];
        #pragma unroll
        for (int i = 0; i < 8; i++) xv[i] = xp[i];
    }
    {
        uint32_t wb = sbase + QW0*4;
        #pragma unroll
        for (int i = 0; i < 6; i++) {
            int idx = tid + i*256;
            int n = idx >> 3, c4 = idx & 7;
            cpa16(wb + (n*36 + c4*4)*4, g_Wth + n*256 + 0 + c4*4);
        }
    }
    CPA_COMMIT();
    #pragma unroll
    for (int i = 0; i < 8; i++) {
        qs[QX0 + xo + i*2]     = packhf(xv[i].y, xv[i].x);
        qs[QX0 + xo + i*2 + 1] = packhf(xv[i].w, xv[i].z);
    }

    for (int it = 0; it < 8; it++) {
        const int cur = it & 1;
        const int xcur = cur ? QX1 : QX0;
        const int xnxt = cur ? QX0 : QX1;
        const int wcur = cur ? QW1 : QW0;
        const int wnxt = cur ? QW0 : QW1;

        if (it < 7) {
            const float4* xp = (const float4*)&x[(r0 + xr) * EMB + (it+1)*64 + xhf*32];
            #pragma unroll
            for (int i = 0; i < 8; i++) xv[i] = xp[i];
            uint32_t wb = sbase + wnxt*4;
            int kw0 = ((it+1)*64) >> 1;
            #pragma unroll
            for (int i = 0; i < 6; i++) {
                int idx = tid + i*256;
                int n = idx >> 3, c4 = idx & 7;
                cpa16(wb + (n*36 + c4*4)*4, g_Wth + n*256 + kw0 + c4*4);
            }
            CPA_COMMIT();
            CPA_WAIT1();
        } else {
            CPA_WAIT0();
        }
        __syncthreads();   // cur buffers ready; prev readers of nxt done

        const uint32_t xb = sbase + xcur*4 + aoff;
        const uint32_t wb2 = sbase + wcur*4 + woffb;
        #pragma unroll
        for (int kk = 0; kk < 4; kk++) {
            unsigned ah[4];
            ldsm4(ah[0], ah[1], ah[2], ah[3], xb + kk*32);
            #pragma unroll
            for (int j2 = 0; j2 < 12; j2++) {
                unsigned b0, b1, b2, b3;
                ldsm4(b0, b1, b2, b3, wb2 + (uint32_t)((j2*2*288 + kk*8) * 4));
                MMAH(C[2*j2],   ah, b0, b1);
                MMAH(C[2*j2+1], ah, b2, b3);
            }
        }

        if (it < 7) {
            #pragma unroll
            for (int i = 0; i < 8; i++) {
                qs[xnxt + xo + i*2]     = packhf(xv[i].y, xv[i].x);
                qs[xnxt + xo + i*2 + 1] = packhf(xv[i].w, xv[i].z);
            }
        }
    }
    __syncthreads();

    // ---- epilogue: Q (j 0..7), K (j 8..15) -> packed fp16 global ----
    const long rowg = r0 + w*16 + g;
    #pragma unroll
    for (int j = 0; j < 16; j++) {
        unsigned* oh = (j < 8) ? g_Qh : g_Kh;
        int wi = (j & 7)*4 + t4;
        oh[rowg*32 + wi]     = packhf(C[j][1], C[j][0]);
        oh[(rowg+8)*32 + wi] = packhf(C[j][3], C[j][2]);
    }

    // ---- V (j 16..23): stage fp32 in smem, transpose+pack to g_Vth ----
    float* vs = (float*)qs;   // [128][66] floats = 8448 w
    #pragma unroll
    for (int j = 16; j < 24; j++) {
        int col = (j - 16)*8 + 2*t4;
        *(float2*)&vs[(w*16 + g)*66 + col]     = make_float2(C[j][0], C[j][1]);
        *(float2*)&vs[(w*16 + g + 8)*66 + col] = make_float2(C[j][2], C[j][3]);
    }
    __syncthreads();

    {
        int b   = (int)(r0 >> 12);
        int kpb = (int)(r0 & 4095) >> 1;
        int kp  = tid & 63;
        int d0  = (tid >> 6) * 16;
        #pragma unroll
        for (int i = 0; i < 16; i++) {
            int d = d0 + i;
            float v0 = vs[(2*kp)*66 + d];
            float v1 = vs[(2*kp + 1)*66 + d];
            g_Vth[((size_t)(b*64 + d)) * 2048 + kpb + kp] = packhf(v1, v0);
        }
    }
}

// ---------------- fp16 HMMA flash attention, cp.async dbl-buffered, occ2, ldmatrix ----
#define BUF_W   8960
#define BK_OFF  0
#define BV_OFF  4608
#define SMEM_BYTES (17920*4)

static __device__ __forceinline__ void attn_issue(uint32_t sbase, int bufw,
                                                  int tid, int b, long brow, int kt) {
    const uint4* KH = (const uint4*)g_Kh + (brow + (long)kt * KT) * 8;
    uint32_t kb = sbase + (bufw + BK_OFF) * 4;
    #pragma unroll
    for (int i = 0; i < 4; i++) {
        int idx = tid + i * 256;
        int r = idx >> 3, c4 = idx & 7;
        cpa16(kb + (r*36 + c4*4)*4, &KH[r*8 + c4]);
    }
    uint32_t vb = sbase + (bufw + BV_OFF) * 4;
    #pragma unroll
    for (int i = 0; i < 4; i++) {
        int idx = tid + i * 256;
        int d = idx >> 4, c4 = idx & 15;
        cpa16(vb + (d*68 + c4*4)*4,
              (const uint4*)g_Vth + ((size_t)(b*64 + d)) * 512 + (size_t)kt * 16 + c4);
    }
}

__global__ __launch_bounds__(256, 2) void attn_mma() {
    extern __shared__ unsigned smw[];
    const uint32_t sbase = smem_u32(smw);

    const int tid  = threadIdx.x;
    const int w    = tid >> 5;
    const int lane = tid & 31;
    const int g    = lane >> 2;
    const int t4   = lane & 3;

    const int Lr = lane & 7, Lm = lane >> 3;
    const uint32_t koff = (uint32_t)((((Lm>>1)*8 + Lr)*36 + (Lm&1)*4) * 4);
    const uint32_t voff = (uint32_t)((((Lm>>1)*8 + Lr)*68 + (Lm&1)*4) * 4);

    // decode (m, split); longest CTAs first (low blockIdx -> largest m)
    int rid = (BLKS_PER_B - 1) - (int)blockIdx.x, m = 0, split = 0;
    #pragma unroll 1
    for (int mm = 0; mm < NMT; mm++) {
        int c = (mm + TPB) >> 3;
        if (rid < c) { m = mm; split = rid; break; }
        rid -= c;
    }
    const int b   = blockIdx.y;
    const int kt0 = split * TPB;
    const int kt1 = (kt0 + TPB < m + 1) ? (kt0 + TPB) : (m + 1);
    const long brow = (long)b * SEQ;
    const int rg = m * MT + w * 16 + g;

    // Q fragments (persist across tiles)
    unsigned qh[4][4];
    {
        long base0 = (brow + rg) * 32;
        long base8 = base0 + 8 * 32;
        #pragma unroll
        for (int kk = 0; kk < 4; kk++) {
            int wlo = 8*kk + t4, whi = wlo + 4;
            qh[kk][0] = g_Qh[base0 + wlo]; qh[kk][1] = g_Qh[base8 + wlo];
            qh[kk][2] = g_Qh[base0 + whi]; qh[kk][3] = g_Qh[base8 + whi];
        }
    }

    float O[8][4];
    #pragma unroll
    for (int i = 0; i < 8; i++)
        #pragma unroll
        for (int j = 0; j < 4; j++) O[i][j] = 0.f;
    float lacc0 = 0.f, lacc1 = 0.f;

    attn_issue(sbase, 0, tid, b, brow, kt0);
    CPA_COMMIT();
    int cur = 0;

    for (int kt = kt0; kt < kt1; kt++) {
        CPA_WAIT0();
        __syncthreads();
        if (kt + 1 < kt1) {
            attn_issue(sbase, (cur ^ 1) * BUF_W, tid, b, brow, kt + 1);
            CPA_COMMIT();
        }
        const uint32_t kbb = sbase + (cur * BUF_W + BK_OFF) * 4 + koff;
        const uint32_t vbb = sbase + (cur * BUF_W + BV_OFF) * 4 + voff;

        const int diag = (kt == m);
        const int kbase = kt * KT;

        #pragma unroll
        for (int h = 0; h < 2; h++) {
            float S[8][4];
            #pragma unroll
            for (int j = 0; j < 8; j++)
                #pragma unroll
                for (int r = 0; r < 4; r++) S[j][r] = 0.f;

            #pragma unroll
            for (int kk = 0; kk < 4; kk++) {
                #pragma unroll
                for (int j2 = 0; j2 < 4; j2++) {
                    unsigned b0, b1, b2, b3;
                    ldsm4(b0, b1, b2, b3,
                          kbb + (uint32_t)(((h*8 + j2*2)*288 + kk*8) * 4));
                    MMAH(S[2*j2],   qh[kk], b0, b1);
                    MMAH(S[2*j2+1], qh[kk], b2, b3);
                }
            }

            unsigned ph[4][4];
            #pragma unroll
            for (int j = 0; j < 8; j++) {
                float p0 = ex2(S[j][0] * SCALE_LOG2E);
                float p1 = ex2(S[j][1] * SCALE_LOG2E);
                float p2 = ex2(S[j][2] * SCALE_LOG2E);
                float p3 = ex2(S[j][3] * SCALE_LOG2E);
                if (diag) {
                    int col = kbase + (h*8 + j)*8 + 2*t4;
                    if (col     > rg)     p0 = 0.f;
                    if (col + 1 > rg)     p1 = 0.f;
                    if (col     > rg + 8) p2 = 0.f;
                    if (col + 1 > rg + 8) p3 = 0.f;
                }
                lacc0 += p0 + p1;
                lacc1 += p2 + p3;
                int kk2 = j >> 1, hf = (j & 1) * 2;
                ph[kk2][hf]     = packhf(p1, p0);
                ph[kk2][hf + 1] = packhf(p3, p2);
            }

            #pragma unroll
            for (int kk2 = 0; kk2 < 4; kk2++) {
                #pragma unroll
                for (int n2p = 0; n2p < 4; n2p++) {
                    unsigned b0, b1, b2, b3;
                    ldsm4(b0, b1, b2, b3,
                          vbb + (uint32_t)((n2p*2*544 + (h*4 + kk2)*8) * 4));
                    MMAH(O[2*n2p],   ph[kk2], b0, b1);
                    MMAH(O[2*n2p+1], ph[kk2], b2, b3);
                }
            }
        }
        cur ^= 1;
    }

    // ---- reduce l over quad, write partials (fp16 O) ----
    lacc0 += __shfl_xor_sync(0xffffffffu, lacc0, 1);
    lacc0 += __shfl_xor_sync(0xffffffffu, lacc0, 2);
    lacc1 += __shfl_xor_sync(0xffffffffu, lacc1, 1);
    lacc1 += __shfl_xor_sync(0xffffffffu, lacc1, 2);

    const int pidx = (b * NMT + m) * MAXSPLIT + split;
    if (t4 == 0) {
        g_Lpart[pidx*128 + w*16 + g]     = lacc0;
        g_Lpart[pidx*128 + w*16 + g + 8] = lacc1;
    }
    unsigned* op0 = g_OpartH + ((size_t)pidx*128 + w*16 + g) * 32;
    unsigned* op8 = op0 + 8*32;
    #pragma unroll
    for (int n2 = 0; n2 < 8; n2++) {
        op0[n2*4 + t4] = packhf(O[n2][1], O[n2][0]);
        op8[n2*4 + t4] = packhf(O[n2][3], O[n2][2]);
    }
}

// ---------------- combine split partials (fp16 in, 8 floats/thread) ----------------
__global__ void combine_kernel(float* __restrict__ out) {
    int idx8 = blockIdx.x * blockDim.x + threadIdx.x;
    if (idx8 >= BS * 8) return;
    int row = idx8 >> 3, d8 = idx8 & 7;
    int b = row >> 12;
    int s_in_b = row & 4095;
    int m = s_in_b >> 7, r = s_in_b & 127;
    int nsp = (m + TPB) >> 3;
    int p0 = (b * NMT + m) * MAXSPLIT;

    uint4 v[4];
    float l[4];
    #pragma unroll
    for (int s = 0; s < 4; s++) {
        v[s] = make_uint4(0u, 0u, 0u, 0u);
        l[s] = 0.f;
        if (s < nsp) {
            int p = p0 + s;
            v[s] = *(const uint4*)&g_OpartH[((size_t)p * 128 + r) * 32 + d8*4];
            l[s] = g_Lpart[p * 128 + r];
        }
    }
    float acc[8];
    #pragma unroll
    for (int i = 0; i < 8; i++) acc[i] = 0.f;
    #pragma unroll
    for (int s = 0; s < 4; s++) {
        unsigned wd[4] = { v[s].x, v[s].y, v[s].z, v[s].w };
        #pragma unroll
        for (int i = 0; i < 4; i++) {
            float2 f = __half22float2(*(__half2*)&wd[i]);
            acc[2*i]   += f.x;
            acc[2*i+1] += f.y;
        }
    }
    float inv = 1.f / (l[0] + l[1] + l[2] + l[3]);
    float* o = out + (size_t)row * 64 + d8*8;
    *(float4*)o       = make_float4(acc[0]*inv, acc[1]*inv, acc[2]*inv, acc[3]*inv);
    *(float4*)(o + 4) = make_float4(acc[4]*inv, acc[5]*inv, acc[6]*inv, acc[7]*inv);
}

extern "C" void kernel_launch(void* const* d_in, const int* in_sizes, int n_in,
                              void* d_out, int out_size) {
    const float* x  = (const float*)d_in[0];
    const float* WQ = (const float*)d_in[1];
    const float* WK = (const float*)d_in[2];
    const float* WV = (const float*)d_in[3];
    float* out = (float*)d_out;

    cudaFuncSetAttribute(qkv_mma,  cudaFuncAttributeMaxDynamicSharedMemorySize, QSMEM_BYTES);
    cudaFuncSetAttribute(attn_mma, cudaFuncAttributeMaxDynamicSharedMemorySize, SMEM_BYTES);

    wprep_kernel<<<192, 256>>>(WQ, WK, WV);
    qkv_mma<<<BS / 128, 256, QSMEM_BYTES>>>(x);
    attn_mma<<<dim3(BLKS_PER_B, BATCH), 256, SMEM_BYTES>>>();
    combine_kernel<<<(BS * 8 + 255) / 256, 256>>>(out);
}